// round 2
// baseline (speedup 1.0000x reference)
#include <cuda_runtime.h>
#include <cstdint>
#include <cstddef>

// ---------------------------------------------------------------------------
// GIN forward on GB300 — fp32 baseline
//   h = x @ W_embed
//   3x: z = (1+eps)*h + scatter_sum(h[src] -> dst);  h = MLP(z)
// Scratch lives in __device__ globals (no allocations allowed).
// ---------------------------------------------------------------------------

#define NNODES 100000

__device__ float g_h[(size_t)NNODES * 128];
__device__ float g_z[(size_t)NNODES * 128];
__device__ float g_t[(size_t)NNODES * 256];
__device__ int   g_is64;

// ---------------------------------------------------------------------------
// Edge-index dtype detection: values are < 2^31, so if the buffer is int64
// every odd 32-bit word is 0. Checked over 128 words -> false positive ~0.
// ---------------------------------------------------------------------------
__global__ void detect_kernel(const int* __restrict__ p) {
    if (threadIdx.x == 0 && blockIdx.x == 0) {
        int is64 = 1;
        for (int j = 0; j < 128; j++) {
            if (p[2 * j + 1] != 0) { is64 = 0; break; }
        }
        g_is64 = is64;
    }
}

// ---------------------------------------------------------------------------
// z = (1 + eps) * h      (grid covers exactly NNODES*128/4 float4s)
// ---------------------------------------------------------------------------
__global__ void init_z_kernel(const float* __restrict__ h, float* __restrict__ z,
                              const float* __restrict__ eps) {
    int i = blockIdx.x * blockDim.x + threadIdx.x;
    float s = 1.0f + eps[0];
    float4 v = ((const float4*)h)[i];
    v.x *= s; v.y *= s; v.z *= s; v.w *= s;
    ((float4*)z)[i] = v;
}

// ---------------------------------------------------------------------------
// Edge scatter: one warp per edge, lane l moves float4 l of the 128-f row.
// Vector reduction (red.global.add.v4.f32, sm_90+) — no return, 16B per op.
// ---------------------------------------------------------------------------
__device__ __forceinline__ void red_add_v4(float* p, float4 v) {
    asm volatile("red.global.add.v4.f32 [%0], {%1, %2, %3, %4};"
                 :: "l"(p), "f"(v.x), "f"(v.y), "f"(v.z), "f"(v.w)
                 : "memory");
}

__global__ void scatter_kernel(const void* __restrict__ eidx,
                               const float* __restrict__ h,
                               float* __restrict__ z, int E) {
    int warp = (blockIdx.x * blockDim.x + threadIdx.x) >> 5;
    int lane = threadIdx.x & 31;
    if (warp >= E) return;
    long long s, d;
    if (g_is64) {
        const long long* p = (const long long*)eidx;
        s = p[warp];
        d = p[E + warp];
    } else {
        const int* p = (const int*)eidx;
        s = p[warp];
        d = p[E + warp];
    }
    float4 v = ((const float4*)(h + s * 128))[lane];
    red_add_v4((float*)(((float4*)(z + d * 128)) + lane), v);
}

// ---------------------------------------------------------------------------
// GEMM: C[M,N] = act(A[M,K] @ W[K,N] + bias)
// Entire W in smem; 32-row A tile in smem; 256 threads; each thread owns a
// 4-row x 4-col x CG microtile (CG = N/128). FMA-bound inner loop:
// per 4 k-steps: 4 LDS.128 (A, broadcast) + 4*CG LDS.128 (W) + 64*CG FFMA.
// ---------------------------------------------------------------------------
template <int K, int N, bool RELU>
__global__ __launch_bounds__(256) void mlp_gemm(const float* __restrict__ A,
                                                const float* __restrict__ W,
                                                const float* __restrict__ bias,
                                                float* __restrict__ C) {
    constexpr int CG = N / 128;
    extern __shared__ float sm[];
    float* Ws = sm;              // K*N floats
    float* As = sm + K * N;      // 32*K floats

    const int tid = threadIdx.x;
    const int m0  = blockIdx.x * 32;

    {
        const float4* Wg  = (const float4*)W;
        float4*       Wsv = (float4*)Ws;
        #pragma unroll 1
        for (int i = tid; i < K * N / 4; i += 256) Wsv[i] = Wg[i];
    }
    {
        const float4* Ag  = (const float4*)(A + (size_t)m0 * K);
        float4*       Asv = (float4*)As;
        #pragma unroll 1
        for (int i = tid; i < 32 * K / 4; i += 256) Asv[i] = Ag[i];
    }
    __syncthreads();

    const int r0 = (tid >> 5) << 2;   // 0..28, row group (same within a warp)
    const int c0 = (tid & 31) << 2;   // 0..124, col group (lane-spread)

    float acc[CG][4][4];
    #pragma unroll
    for (int g = 0; g < CG; g++)
        #pragma unroll
        for (int i = 0; i < 4; i++)
            #pragma unroll
            for (int j = 0; j < 4; j++) acc[g][i][j] = 0.0f;

    #pragma unroll 4
    for (int k = 0; k < K; k += 4) {
        float4 a[4];
        #pragma unroll
        for (int i = 0; i < 4; i++)
            a[i] = *(const float4*)&As[(r0 + i) * K + k];

        #pragma unroll
        for (int kk = 0; kk < 4; kk++) {
            float4 b[CG];
            #pragma unroll
            for (int g = 0; g < CG; g++)
                b[g] = *(const float4*)&Ws[(k + kk) * N + (g << 7) + c0];
            #pragma unroll
            for (int i = 0; i < 4; i++) {
                float av = (kk == 0) ? a[i].x : (kk == 1) ? a[i].y
                          : (kk == 2) ? a[i].z : a[i].w;
                #pragma unroll
                for (int g = 0; g < CG; g++) {
                    acc[g][i][0] = fmaf(av, b[g].x, acc[g][i][0]);
                    acc[g][i][1] = fmaf(av, b[g].y, acc[g][i][1]);
                    acc[g][i][2] = fmaf(av, b[g].z, acc[g][i][2]);
                    acc[g][i][3] = fmaf(av, b[g].w, acc[g][i][3]);
                }
            }
        }
    }

    #pragma unroll
    for (int g = 0; g < CG; g++) {
        float4 bv = make_float4(0.f, 0.f, 0.f, 0.f);
        if (bias) bv = *(const float4*)&bias[(g << 7) + c0];
        #pragma unroll
        for (int i = 0; i < 4; i++) {
            float4 o;
            o.x = acc[g][i][0] + bv.x;
            o.y = acc[g][i][1] + bv.y;
            o.z = acc[g][i][2] + bv.z;
            o.w = acc[g][i][3] + bv.w;
            if (RELU) {
                o.x = fmaxf(o.x, 0.f); o.y = fmaxf(o.y, 0.f);
                o.z = fmaxf(o.z, 0.f); o.w = fmaxf(o.w, 0.f);
            }
            *(float4*)&C[(size_t)(m0 + r0 + i) * N + (g << 7) + c0] = o;
        }
    }
}

// ---------------------------------------------------------------------------
// Host launcher
// ---------------------------------------------------------------------------
template <int K, int N, bool RELU>
static void launch_gemm(const float* A, const float* W, const float* bias,
                        float* C, int M) {
    size_t smem = (size_t)(K * N + 32 * K) * sizeof(float);
    cudaFuncSetAttribute(mlp_gemm<K, N, RELU>,
                         cudaFuncAttributeMaxDynamicSharedMemorySize, (int)smem);
    mlp_gemm<K, N, RELU><<<M / 32, 256, smem>>>(A, W, bias, C);
}

extern "C" void kernel_launch(void* const* d_in, const int* in_sizes, int n_in,
                              void* d_out, int out_size) {
    const float* x       = (const float*)d_in[0];
    const void*  eidx    = d_in[1];
    const float* W_embed = (const float*)d_in[2];
    const float* eps1    = (const float*)d_in[3];
    const float* w1a     = (const float*)d_in[4];
    const float* b1a     = (const float*)d_in[5];
    const float* w1b     = (const float*)d_in[6];
    const float* b1b     = (const float*)d_in[7];
    const float* eps2    = (const float*)d_in[8];
    const float* w2a     = (const float*)d_in[9];
    const float* b2a     = (const float*)d_in[10];
    const float* w2b     = (const float*)d_in[11];
    const float* b2b     = (const float*)d_in[12];
    const float* eps3    = (const float*)d_in[13];
    const float* w3a     = (const float*)d_in[14];
    const float* b3a     = (const float*)d_in[15];
    const float* w3b     = (const float*)d_in[16];
    const float* b3b     = (const float*)d_in[17];

    const int M = in_sizes[0] / 64;          // 100000 nodes
    const int E = in_sizes[1] / 2;           // 1600000 edges

    float *ph, *pz, *pt;
    cudaGetSymbolAddress((void**)&ph, g_h);
    cudaGetSymbolAddress((void**)&pz, g_z);
    cudaGetSymbolAddress((void**)&pt, g_t);
    float* out = (float*)d_out;

    const int elem4     = M * 128 / 4;                 // float4 count
    const int initBlks  = (elem4 + 255) / 256;
    const int scatBlks  = (E + 7) / 8;                 // 1 warp per edge

    detect_kernel<<<1, 1>>>((const int*)eidx);

    // ---- embed: h = x @ W_embed ----
    launch_gemm<64, 128, false>(x, W_embed, nullptr, ph, M);

    // ---- conv1 ----
    init_z_kernel<<<initBlks, 256>>>(ph, pz, eps1);
    scatter_kernel<<<scatBlks, 256>>>(eidx, ph, pz, E);
    launch_gemm<128, 128, true >(pz, w1a, b1a, pt, M);
    launch_gemm<128, 128, false>(pt, w1b, b1b, ph, M);

    // ---- conv2 ----
    init_z_kernel<<<initBlks, 256>>>(ph, pz, eps2);
    scatter_kernel<<<scatBlks, 256>>>(eidx, ph, pz, E);
    launch_gemm<128, 256, true>(pz, w2a, b2a, pt, M);
    launch_gemm<256, 128, true>(pt, w2b, b2b, ph, M);

    // ---- conv3 ----
    init_z_kernel<<<initBlks, 256>>>(ph, pz, eps3);
    scatter_kernel<<<scatBlks, 256>>>(eidx, ph, pz, E);
    launch_gemm<128, 256, true>(pz, w3a, b3a, pt, M);
    launch_gemm<256, 128, true>(pt, w3b, b3b, out, M);
}

// round 3
// speedup vs baseline: 1.6269x; 1.6269x over previous
#include <cuda_runtime.h>
#include <cuda_bf16.h>
#include <cstdint>
#include <cstddef>

// ---------------------------------------------------------------------------
// GIN forward on GB300 — tensor-core (bf16 split-precision) version
//   h = x @ W_embed ; 3x: z = (1+eps)h + scatter_sum(h[src]->dst); h = MLP(z)
// GEMMs use mma.sync.m16n8k16 bf16 with 2-way bf16 operand splitting
// (3-term product) for ~fp32 accuracy at tensor-core speed.
// ---------------------------------------------------------------------------

#define NNODES 100000

__device__ float g_h[(size_t)NNODES * 128];
__device__ float g_z[(size_t)NNODES * 128];
__device__ float g_t[(size_t)NNODES * 256];
__device__ int   g_is64;
__device__ __nv_bfloat16 g_whi[32768];   // max K*N = 256*128
__device__ __nv_bfloat16 g_wlo[32768];

// ---------------------------------------------------------------------------
// Edge-index dtype detection (int64 vs int32): values < 2^31 so int64 buffers
// have every odd 32-bit word == 0.
// ---------------------------------------------------------------------------
__global__ void detect_kernel(const int* __restrict__ p) {
    if (threadIdx.x == 0 && blockIdx.x == 0) {
        int is64 = 1;
        for (int j = 0; j < 128; j++) {
            if (p[2 * j + 1] != 0) { is64 = 0; break; }
        }
        g_is64 = is64;
    }
}

// ---------------------------------------------------------------------------
// z = (1 + eps) * h
// ---------------------------------------------------------------------------
__global__ void init_z_kernel(const float* __restrict__ h, float* __restrict__ z,
                              const float* __restrict__ eps) {
    int i = blockIdx.x * blockDim.x + threadIdx.x;
    float s = 1.0f + eps[0];
    float4 v = ((const float4*)h)[i];
    v.x *= s; v.y *= s; v.z *= s; v.w *= s;
    ((float4*)z)[i] = v;
}

// ---------------------------------------------------------------------------
// Edge scatter: one warp per 4 edges (MLP=4). Lane l moves float4 l of the
// 128-float row. Vector reduction red.global.add.v4.f32.
// ---------------------------------------------------------------------------
__device__ __forceinline__ void red_add_v4(float* p, float4 v) {
    asm volatile("red.global.add.v4.f32 [%0], {%1, %2, %3, %4};"
                 :: "l"(p), "f"(v.x), "f"(v.y), "f"(v.z), "f"(v.w)
                 : "memory");
}

__global__ void scatter_kernel(const void* __restrict__ eidx,
                               const float* __restrict__ h,
                               float* __restrict__ z, int E) {
    int warp = (blockIdx.x * blockDim.x + threadIdx.x) >> 5;
    int lane = threadIdx.x & 31;
    int e0 = warp * 4;
    if (e0 >= E) return;

    int idxv = 0;
    if (lane < 8) {
        int e = e0 + (lane & 3);
        if (e < E) {
            if (g_is64) {
                const long long* p = (const long long*)eidx;
                idxv = (int)((lane < 4) ? p[e] : p[E + e]);
            } else {
                const int* p = (const int*)eidx;
                idxv = (lane < 4) ? p[e] : p[E + e];
            }
        }
    }
    int s[4], d[4];
    #pragma unroll
    for (int j = 0; j < 4; j++) {
        s[j] = __shfl_sync(0xffffffffu, idxv, j);
        d[j] = __shfl_sync(0xffffffffu, idxv, 4 + j);
    }
    float4 v[4];
    #pragma unroll
    for (int j = 0; j < 4; j++)
        v[j] = ((const float4*)(h + (size_t)s[j] * 128))[lane];
    #pragma unroll
    for (int j = 0; j < 4; j++) {
        if (e0 + j < E)
            red_add_v4((float*)(((float4*)(z + (size_t)d[j] * 128)) + lane), v[j]);
    }
}

// ---------------------------------------------------------------------------
// Weight prep: W[K][N] fp32 -> transposed bf16 hi/lo pair Wt[N][K].
// hi = bf16(x), lo = bf16(x - hi). Tiny, runs once per GEMM.
// ---------------------------------------------------------------------------
__global__ void wprep_kernel(const float* __restrict__ W,
                             __nv_bfloat16* __restrict__ whi,
                             __nv_bfloat16* __restrict__ wlo, int K, int N) {
    int i = blockIdx.x * blockDim.x + threadIdx.x;
    if (i >= K * N) return;
    int k = i / N, n = i % N;
    float x = W[i];
    __nv_bfloat16 h = __float2bfloat16(x);
    float r = x - __bfloat162float(h);
    whi[n * K + k] = h;
    wlo[n * K + k] = __float2bfloat16(r);
}

// ---------------------------------------------------------------------------
// Tensor-core GEMM: C[M,NTOT] = act(A[M,K] @ W[K,NTOT] + bias)
// CTA tile 128x128, BK=32. 8 warps in 4x2; warp tile 32x64.
// mma.sync.m16n8k16 bf16, 3-term split: Ah*Bh + Al*Bh + Ah*Bl.
// Smem rows padded to 40 bf16 (stride 20 words mod 32 -> conflict-free frags).
// ---------------------------------------------------------------------------
__device__ __forceinline__ void mma_bf16(float c[4], const uint32_t a[4],
                                         uint32_t b0, uint32_t b1) {
    asm volatile(
        "mma.sync.aligned.m16n8k16.row.col.f32.bf16.bf16.f32 "
        "{%0,%1,%2,%3}, {%4,%5,%6,%7}, {%8,%9}, {%0,%1,%2,%3};"
        : "+f"(c[0]), "+f"(c[1]), "+f"(c[2]), "+f"(c[3])
        : "r"(a[0]), "r"(a[1]), "r"(a[2]), "r"(a[3]), "r"(b0), "r"(b1));
}

__device__ __forceinline__ uint32_t pack_bf16x2(__nv_bfloat16 x, __nv_bfloat16 y) {
    __nv_bfloat162 p = __halves2bfloat162(x, y);
    return *reinterpret_cast<uint32_t*>(&p);
}

template <int K, int NTOT, bool RELU>
__global__ __launch_bounds__(256, 2) void mma_gemm(
    const float* __restrict__ A,
    const __nv_bfloat16* __restrict__ Wh,
    const __nv_bfloat16* __restrict__ Wl,
    const float* __restrict__ bias,
    float* __restrict__ C, int M) {

    __shared__ __nv_bfloat16 Ah[128][40];
    __shared__ __nv_bfloat16 Al[128][40];
    __shared__ __nv_bfloat16 Bh[128][40];
    __shared__ __nv_bfloat16 Bl[128][40];

    const int tid  = threadIdx.x;
    const int lane = tid & 31;
    const int warp = tid >> 5;
    const int wm   = warp >> 1;      // 0..3
    const int wn   = warp & 1;       // 0..1
    const int m0   = blockIdx.x * 128;
    const int n0   = blockIdx.y * 128;
    const int g    = lane >> 2;      // 0..7
    const int q4   = lane & 3;       // 0..3

    float acc[2][8][4];
    #pragma unroll
    for (int mt = 0; mt < 2; mt++)
        #pragma unroll
        for (int nt = 0; nt < 8; nt++)
            #pragma unroll
            for (int j = 0; j < 4; j++) acc[mt][nt][j] = 0.0f;

    for (int k0 = 0; k0 < K; k0 += 32) {
        // ---- load + split A tile: 128 rows x 32 k (fp32 -> bf16 hi/lo) ----
        #pragma unroll
        for (int i = tid; i < 1024; i += 256) {
            int row = i >> 3, kq = i & 7;
            int gr = m0 + row;
            float4 v = make_float4(0.f, 0.f, 0.f, 0.f);
            if (gr < M)
                v = *(const float4*)(A + (size_t)gr * K + k0 + kq * 4);
            __nv_bfloat16 h0 = __float2bfloat16(v.x), h1 = __float2bfloat16(v.y);
            __nv_bfloat16 h2 = __float2bfloat16(v.z), h3 = __float2bfloat16(v.w);
            __nv_bfloat16 l0 = __float2bfloat16(v.x - __bfloat162float(h0));
            __nv_bfloat16 l1 = __float2bfloat16(v.y - __bfloat162float(h1));
            __nv_bfloat16 l2 = __float2bfloat16(v.z - __bfloat162float(h2));
            __nv_bfloat16 l3 = __float2bfloat16(v.w - __bfloat162float(h3));
            uint2 ph = make_uint2(pack_bf16x2(h0, h1), pack_bf16x2(h2, h3));
            uint2 pl = make_uint2(pack_bf16x2(l0, l1), pack_bf16x2(l2, l3));
            *(uint2*)&Ah[row][kq * 4] = ph;
            *(uint2*)&Al[row][kq * 4] = pl;
        }
        // ---- load W tile (already transposed bf16 [N][K]): 128 n x 32 k ----
        #pragma unroll
        for (int i = tid; i < 512; i += 256) {
            int n = i >> 2, q = i & 3;
            const size_t off = (size_t)(n0 + n) * K + k0 + q * 8;
            uint4 vh = *(const uint4*)(Wh + off);
            uint4 vl = *(const uint4*)(Wl + off);
            *(uint4*)&Bh[n][q * 8] = vh;
            *(uint4*)&Bl[n][q * 8] = vl;
        }
        __syncthreads();

        #pragma unroll
        for (int ks = 0; ks < 32; ks += 16) {
            const int kc = ks + q4 * 2;
            uint32_t ah[2][4], al[2][4];
            #pragma unroll
            for (int mt = 0; mt < 2; mt++) {
                int r = wm * 32 + mt * 16 + g;
                ah[mt][0] = *(const uint32_t*)&Ah[r][kc];
                ah[mt][1] = *(const uint32_t*)&Ah[r + 8][kc];
                ah[mt][2] = *(const uint32_t*)&Ah[r][kc + 8];
                ah[mt][3] = *(const uint32_t*)&Ah[r + 8][kc + 8];
                al[mt][0] = *(const uint32_t*)&Al[r][kc];
                al[mt][1] = *(const uint32_t*)&Al[r + 8][kc];
                al[mt][2] = *(const uint32_t*)&Al[r][kc + 8];
                al[mt][3] = *(const uint32_t*)&Al[r + 8][kc + 8];
            }
            #pragma unroll
            for (int nt = 0; nt < 8; nt++) {
                int n = wn * 64 + nt * 8 + g;
                uint32_t bh0 = *(const uint32_t*)&Bh[n][kc];
                uint32_t bh1 = *(const uint32_t*)&Bh[n][kc + 8];
                uint32_t bl0 = *(const uint32_t*)&Bl[n][kc];
                uint32_t bl1 = *(const uint32_t*)&Bl[n][kc + 8];
                #pragma unroll
                for (int mt = 0; mt < 2; mt++) {
                    mma_bf16(acc[mt][nt], ah[mt], bh0, bh1);
                    mma_bf16(acc[mt][nt], al[mt], bh0, bh1);
                    mma_bf16(acc[mt][nt], ah[mt], bl0, bl1);
                }
            }
        }
        __syncthreads();
    }

    // ---- epilogue: bias + activation + guarded store ----
    #pragma unroll
    for (int mt = 0; mt < 2; mt++) {
        #pragma unroll
        for (int nt = 0; nt < 8; nt++) {
            int c = n0 + wn * 64 + nt * 8 + 2 * q4;
            float2 bv = make_float2(0.f, 0.f);
            if (bias) bv = *(const float2*)&bias[c];
            int r = m0 + wm * 32 + mt * 16 + g;
            float2 o0, o1;
            o0.x = acc[mt][nt][0] + bv.x;
            o0.y = acc[mt][nt][1] + bv.y;
            o1.x = acc[mt][nt][2] + bv.x;
            o1.y = acc[mt][nt][3] + bv.y;
            if (RELU) {
                o0.x = fmaxf(o0.x, 0.f); o0.y = fmaxf(o0.y, 0.f);
                o1.x = fmaxf(o1.x, 0.f); o1.y = fmaxf(o1.y, 0.f);
            }
            if (r < M)     *(float2*)&C[(size_t)r * NTOT + c]       = o0;
            if (r + 8 < M) *(float2*)&C[(size_t)(r + 8) * NTOT + c] = o1;
        }
    }
}

// ---------------------------------------------------------------------------
// Host side
// ---------------------------------------------------------------------------
static __nv_bfloat16 *s_whi, *s_wlo;

template <int K, int NTOT, bool RELU>
static void run_gemm(const float* A, const float* W, const float* bias,
                     float* C, int M) {
    wprep_kernel<<<(K * NTOT + 255) / 256, 256>>>(W, s_whi, s_wlo, K, NTOT);
    dim3 grid((M + 127) / 128, NTOT / 128);
    mma_gemm<K, NTOT, RELU><<<grid, 256>>>(A, s_whi, s_wlo, bias, C, M);
}

extern "C" void kernel_launch(void* const* d_in, const int* in_sizes, int n_in,
                              void* d_out, int out_size) {
    const float* x       = (const float*)d_in[0];
    const void*  eidx    = d_in[1];
    const float* W_embed = (const float*)d_in[2];
    const float* eps1    = (const float*)d_in[3];
    const float* w1a     = (const float*)d_in[4];
    const float* b1a     = (const float*)d_in[5];
    const float* w1b     = (const float*)d_in[6];
    const float* b1b     = (const float*)d_in[7];
    const float* eps2    = (const float*)d_in[8];
    const float* w2a     = (const float*)d_in[9];
    const float* b2a     = (const float*)d_in[10];
    const float* w2b     = (const float*)d_in[11];
    const float* b2b     = (const float*)d_in[12];
    const float* eps3    = (const float*)d_in[13];
    const float* w3a     = (const float*)d_in[14];
    const float* b3a     = (const float*)d_in[15];
    const float* w3b     = (const float*)d_in[16];
    const float* b3b     = (const float*)d_in[17];

    const int M = in_sizes[0] / 64;          // 100000 nodes
    const int E = in_sizes[1] / 2;           // 1600000 edges

    float *ph, *pz, *pt;
    cudaGetSymbolAddress((void**)&ph, g_h);
    cudaGetSymbolAddress((void**)&pz, g_z);
    cudaGetSymbolAddress((void**)&pt, g_t);
    cudaGetSymbolAddress((void**)&s_whi, g_whi);
    cudaGetSymbolAddress((void**)&s_wlo, g_wlo);
    float* out = (float*)d_out;

    const int elem4    = M * 128 / 4;
    const int initBlks = (elem4 + 255) / 256;
    const int scatBlks = (E + 31) / 32;      // 4 edges per warp, 8 warps/block

    detect_kernel<<<1, 1>>>((const int*)eidx);

    // ---- embed: h = x @ W_embed ----
    run_gemm<64, 128, false>(x, W_embed, nullptr, ph, M);

    // ---- conv1 ----
    init_z_kernel<<<initBlks, 256>>>(ph, pz, eps1);
    scatter_kernel<<<scatBlks, 256>>>(eidx, ph, pz, E);
    run_gemm<128, 128, true >(pz, w1a, b1a, pt, M);
    run_gemm<128, 128, false>(pt, w1b, b1b, ph, M);

    // ---- conv2 ----
    init_z_kernel<<<initBlks, 256>>>(ph, pz, eps2);
    scatter_kernel<<<scatBlks, 256>>>(eidx, ph, pz, E);
    run_gemm<128, 256, true>(pz, w2a, b2a, pt, M);
    run_gemm<256, 128, true>(pt, w2b, b2b, ph, M);

    // ---- conv3 ----
    init_z_kernel<<<initBlks, 256>>>(ph, pz, eps3);
    scatter_kernel<<<scatBlks, 256>>>(eidx, ph, pz, E);
    run_gemm<128, 256, true>(pz, w3a, b3a, pt, M);
    run_gemm<256, 128, true>(pt, w3b, b3b, out, M);
}

// round 4
// speedup vs baseline: 2.6898x; 1.6533x over previous
#include <cuda_runtime.h>
#include <cuda_bf16.h>
#include <cstdint>
#include <cstddef>

// ---------------------------------------------------------------------------
// GIN forward on GB300 — tensor-core (bf16 split-precision) version, R4
//   h = x @ W_embed ; 3x: z = (1+eps)h + scatter_sum(h[src]->dst); h = MLP(z)
// R4: ldmatrix fragment loads, init_z fused into GEMM epilogue,
//     single weight-prep kernel, cp.async weight tiles.
// ---------------------------------------------------------------------------

#define NNODES 100000
#define WTOTAL 172032   // sum of all 7 weight matrices' elements

__device__ float g_h[(size_t)NNODES * 128];
__device__ float g_z[(size_t)NNODES * 128];
__device__ float g_t[(size_t)NNODES * 256];
__device__ int   g_is64;
__device__ __nv_bfloat16 g_whi[WTOTAL];
__device__ __nv_bfloat16 g_wlo[WTOTAL];

// ---------------------------------------------------------------------------
// Edge-index dtype detection (int64 vs int32)
// ---------------------------------------------------------------------------
__global__ void detect_kernel(const int* __restrict__ p) {
    if (threadIdx.x == 0 && blockIdx.x == 0) {
        int is64 = 1;
        for (int j = 0; j < 128; j++) {
            if (p[2 * j + 1] != 0) { is64 = 0; break; }
        }
        g_is64 = is64;
    }
}

// ---------------------------------------------------------------------------
// Weight prep (all 7 at once): W[K][N] fp32 -> transposed bf16 hi/lo [N][K]
// ---------------------------------------------------------------------------
struct WSeg { const float* src; int K, N, off; };
struct WAll { WSeg s[7]; };

__global__ void wprep_all(WAll wa, __nv_bfloat16* __restrict__ hi,
                          __nv_bfloat16* __restrict__ lo) {
    int i = blockIdx.x * blockDim.x + threadIdx.x;
    #pragma unroll
    for (int j = 0; j < 7; j++) {
        WSeg sg = wa.s[j];
        int loc = i - sg.off;
        if (loc >= 0 && loc < sg.K * sg.N) {
            int k = loc / sg.N, n = loc % sg.N;
            float x = sg.src[loc];
            __nv_bfloat16 h = __float2bfloat16(x);
            hi[sg.off + n * sg.K + k] = h;
            lo[sg.off + n * sg.K + k] = __float2bfloat16(x - __bfloat162float(h));
        }
    }
}

// ---------------------------------------------------------------------------
// Edge scatter: one warp per 4 edges. Lane l moves float4 l of the row.
// ---------------------------------------------------------------------------
__device__ __forceinline__ void red_add_v4(float* p, float4 v) {
    asm volatile("red.global.add.v4.f32 [%0], {%1, %2, %3, %4};"
                 :: "l"(p), "f"(v.x), "f"(v.y), "f"(v.z), "f"(v.w)
                 : "memory");
}

__global__ void scatter_kernel(const void* __restrict__ eidx,
                               const float* __restrict__ h,
                               float* __restrict__ z, int E) {
    int warp = (blockIdx.x * blockDim.x + threadIdx.x) >> 5;
    int lane = threadIdx.x & 31;
    int e0 = warp * 4;
    if (e0 >= E) return;

    int idxv = 0;
    if (lane < 8) {
        int e = e0 + (lane & 3);
        if (e < E) {
            if (g_is64) {
                const long long* p = (const long long*)eidx;
                idxv = (int)((lane < 4) ? p[e] : p[E + e]);
            } else {
                const int* p = (const int*)eidx;
                idxv = (lane < 4) ? p[e] : p[E + e];
            }
        }
    }
    int s[4], d[4];
    #pragma unroll
    for (int j = 0; j < 4; j++) {
        s[j] = __shfl_sync(0xffffffffu, idxv, j);
        d[j] = __shfl_sync(0xffffffffu, idxv, 4 + j);
    }
    float4 v[4];
    #pragma unroll
    for (int j = 0; j < 4; j++)
        v[j] = ((const float4*)(h + (size_t)s[j] * 128))[lane];
    #pragma unroll
    for (int j = 0; j < 4; j++) {
        if (e0 + j < E)
            red_add_v4((float*)(((float4*)(z + (size_t)d[j] * 128)) + lane), v[j]);
    }
}

// ---------------------------------------------------------------------------
// MMA helpers
// ---------------------------------------------------------------------------
__device__ __forceinline__ void mma_bf16(float c[4], const uint32_t a[4],
                                         uint32_t b0, uint32_t b1) {
    asm volatile(
        "mma.sync.aligned.m16n8k16.row.col.f32.bf16.bf16.f32 "
        "{%0,%1,%2,%3}, {%4,%5,%6,%7}, {%8,%9}, {%0,%1,%2,%3};"
        : "+f"(c[0]), "+f"(c[1]), "+f"(c[2]), "+f"(c[3])
        : "r"(a[0]), "r"(a[1]), "r"(a[2]), "r"(a[3]), "r"(b0), "r"(b1));
}

__device__ __forceinline__ void ldsm_x4(uint32_t r[4], uint32_t saddr) {
    asm volatile("ldmatrix.sync.aligned.m8n8.x4.shared.b16 {%0,%1,%2,%3}, [%4];"
                 : "=r"(r[0]), "=r"(r[1]), "=r"(r[2]), "=r"(r[3])
                 : "r"(saddr));
}

__device__ __forceinline__ void cp16(uint32_t saddr, const void* gaddr) {
    asm volatile("cp.async.ca.shared.global [%0], [%1], 16;"
                 :: "r"(saddr), "l"(gaddr) : "memory");
}

__device__ __forceinline__ uint32_t pack_bf16x2(__nv_bfloat16 x, __nv_bfloat16 y) {
    __nv_bfloat162 p = __halves2bfloat162(x, y);
    return *reinterpret_cast<uint32_t*>(&p);
}

// ---------------------------------------------------------------------------
// Tensor-core GEMM: C = act(A[M,K] @ W[K,NTOT] + bias); optional fused
// z = (1+eps)*C epilogue. CTA tile 128x128, BK=32, 8 warps (4x2), warp 32x64.
// bf16 split: Ah*Bh + Al*Bh + Ah*Bl. ldmatrix fragment loads.
// ---------------------------------------------------------------------------
template <int K, int NTOT, bool RELU>
__global__ __launch_bounds__(256, 2) void mma_gemm(
    const float* __restrict__ A,
    const __nv_bfloat16* __restrict__ Wh,
    const __nv_bfloat16* __restrict__ Wl,
    const float* __restrict__ bias,
    float* __restrict__ C,
    float* __restrict__ zout, const float* __restrict__ eps,
    int M) {

    __shared__ __nv_bfloat16 Ah[128][40];
    __shared__ __nv_bfloat16 Al[128][40];
    __shared__ __nv_bfloat16 Bh[128][40];
    __shared__ __nv_bfloat16 Bl[128][40];

    const int tid  = threadIdx.x;
    const int lane = tid & 31;
    const int warp = tid >> 5;
    const int wm   = warp >> 1;      // 0..3
    const int wn   = warp & 1;       // 0..1
    const int m0   = blockIdx.x * 128;
    const int n0   = blockIdx.y * 128;
    const int g    = lane >> 2;      // 0..7
    const int q4   = lane & 3;       // 0..3

    // ldmatrix per-lane source rows/cols
    const int arow = (lane & 7) + ((lane >> 3) & 1) * 8;  // row within 16
    const int akq  = (lane >> 4) * 8;                     // k offset 0/8
    const int bn   = (lane & 7) + ((lane >> 4) & 1) * 8;  // n within 16
    const int bkq  = ((lane >> 3) & 1) * 8;               // k offset 0/8

    uint32_t sAh = (uint32_t)__cvta_generic_to_shared(&Ah[0][0]);
    uint32_t sAl = (uint32_t)__cvta_generic_to_shared(&Al[0][0]);
    uint32_t sBh = (uint32_t)__cvta_generic_to_shared(&Bh[0][0]);
    uint32_t sBl = (uint32_t)__cvta_generic_to_shared(&Bl[0][0]);

    uint32_t aBaseH[2], aBaseL[2], bBaseH[4], bBaseL[4];
    #pragma unroll
    for (int mt = 0; mt < 2; mt++) {
        int r = wm * 32 + mt * 16 + arow;
        aBaseH[mt] = sAh + (uint32_t)(r * 40 + akq) * 2;
        aBaseL[mt] = sAl + (uint32_t)(r * 40 + akq) * 2;
    }
    #pragma unroll
    for (int ntp = 0; ntp < 4; ntp++) {
        int n = wn * 64 + ntp * 16 + bn;
        bBaseH[ntp] = sBh + (uint32_t)(n * 40 + bkq) * 2;
        bBaseL[ntp] = sBl + (uint32_t)(n * 40 + bkq) * 2;
    }

    float acc[2][8][4];
    #pragma unroll
    for (int mt = 0; mt < 2; mt++)
        #pragma unroll
        for (int nt = 0; nt < 8; nt++)
            #pragma unroll
            for (int j = 0; j < 4; j++) acc[mt][nt][j] = 0.0f;

    for (int k0 = 0; k0 < K; k0 += 32) {
        // ---- async-copy W tile (bf16, transposed [N][K]) ----
        {
            int n = tid >> 1, q = tid & 1;           // 2 chunks of 16B per row pair
            // 128 rows x 4 chunks = 512; 256 threads -> 2 per thread per array
            #pragma unroll
            for (int rep = 0; rep < 2; rep++) {
                int i = tid + rep * 256;             // 0..511
                n = i >> 2; q = i & 3;
                const size_t off = (size_t)(n0 + n) * K + k0 + q * 8;
                cp16(sBh + (uint32_t)(n * 40 + q * 8) * 2, Wh + off);
                cp16(sBl + (uint32_t)(n * 40 + q * 8) * 2, Wl + off);
            }
            asm volatile("cp.async.commit_group;");
        }
        // ---- load + split A tile: 128 rows x 32 k (fp32 -> bf16 hi/lo) ----
        #pragma unroll
        for (int i = tid; i < 1024; i += 256) {
            int row = i >> 3, kq = i & 7;
            int gr = m0 + row;
            float4 v = make_float4(0.f, 0.f, 0.f, 0.f);
            if (gr < M)
                v = *(const float4*)(A + (size_t)gr * K + k0 + kq * 4);
            __nv_bfloat16 h0 = __float2bfloat16(v.x), h1 = __float2bfloat16(v.y);
            __nv_bfloat16 h2 = __float2bfloat16(v.z), h3 = __float2bfloat16(v.w);
            __nv_bfloat16 l0 = __float2bfloat16(v.x - __bfloat162float(h0));
            __nv_bfloat16 l1 = __float2bfloat16(v.y - __bfloat162float(h1));
            __nv_bfloat16 l2 = __float2bfloat16(v.z - __bfloat162float(h2));
            __nv_bfloat16 l3 = __float2bfloat16(v.w - __bfloat162float(h3));
            *(uint2*)&Ah[row][kq * 4] =
                make_uint2(pack_bf16x2(h0, h1), pack_bf16x2(h2, h3));
            *(uint2*)&Al[row][kq * 4] =
                make_uint2(pack_bf16x2(l0, l1), pack_bf16x2(l2, l3));
        }
        asm volatile("cp.async.wait_group 0;");
        __syncthreads();

        #pragma unroll
        for (int ks = 0; ks < 32; ks += 16) {
            const uint32_t kofs = (uint32_t)ks * 2;
            uint32_t ah[2][4], al[2][4];
            #pragma unroll
            for (int mt = 0; mt < 2; mt++) {
                ldsm_x4(ah[mt], aBaseH[mt] + kofs);
                ldsm_x4(al[mt], aBaseL[mt] + kofs);
            }
            uint32_t bh[4][4];
            #pragma unroll
            for (int ntp = 0; ntp < 4; ntp++)
                ldsm_x4(bh[ntp], bBaseH[ntp] + kofs);
            #pragma unroll
            for (int nt = 0; nt < 8; nt++) {
                uint32_t b0 = bh[nt >> 1][(nt & 1) * 2];
                uint32_t b1 = bh[nt >> 1][(nt & 1) * 2 + 1];
                #pragma unroll
                for (int mt = 0; mt < 2; mt++) {
                    mma_bf16(acc[mt][nt], ah[mt], b0, b1);
                    mma_bf16(acc[mt][nt], al[mt], b0, b1);
                }
            }
            uint32_t bl[4][4];
            #pragma unroll
            for (int ntp = 0; ntp < 4; ntp++)
                ldsm_x4(bl[ntp], bBaseL[ntp] + kofs);
            #pragma unroll
            for (int nt = 0; nt < 8; nt++) {
                uint32_t b0 = bl[nt >> 1][(nt & 1) * 2];
                uint32_t b1 = bl[nt >> 1][(nt & 1) * 2 + 1];
                #pragma unroll
                for (int mt = 0; mt < 2; mt++)
                    mma_bf16(acc[mt][nt], ah[mt], b0, b1);
            }
        }
        __syncthreads();
    }

    // ---- epilogue: bias + activation (+ fused z) + guarded store ----
    const float zs = zout ? (1.0f + __ldg(eps)) : 0.0f;
    #pragma unroll
    for (int mt = 0; mt < 2; mt++) {
        #pragma unroll
        for (int nt = 0; nt < 8; nt++) {
            int c = n0 + wn * 64 + nt * 8 + 2 * q4;
            float2 bv = make_float2(0.f, 0.f);
            if (bias) bv = *(const float2*)&bias[c];
            int r = m0 + wm * 32 + mt * 16 + g;
            float2 o0, o1;
            o0.x = acc[mt][nt][0] + bv.x;
            o0.y = acc[mt][nt][1] + bv.y;
            o1.x = acc[mt][nt][2] + bv.x;
            o1.y = acc[mt][nt][3] + bv.y;
            if (RELU) {
                o0.x = fmaxf(o0.x, 0.f); o0.y = fmaxf(o0.y, 0.f);
                o1.x = fmaxf(o1.x, 0.f); o1.y = fmaxf(o1.y, 0.f);
            }
            if (r < M) {
                *(float2*)&C[(size_t)r * NTOT + c] = o0;
                if (zout) {
                    float2 zv = make_float2(o0.x * zs, o0.y * zs);
                    *(float2*)&zout[(size_t)r * NTOT + c] = zv;
                }
            }
            if (r + 8 < M) {
                *(float2*)&C[(size_t)(r + 8) * NTOT + c] = o1;
                if (zout) {
                    float2 zv = make_float2(o1.x * zs, o1.y * zs);
                    *(float2*)&zout[(size_t)(r + 8) * NTOT + c] = zv;
                }
            }
        }
    }
}

// ---------------------------------------------------------------------------
// Host side
// ---------------------------------------------------------------------------
static __nv_bfloat16 *s_whi, *s_wlo;

template <int K, int NTOT, bool RELU>
static void run_gemm(const float* A, int woff, const float* bias, float* C,
                     float* zout, const float* eps, int M) {
    dim3 grid((M + 127) / 128, NTOT / 128);
    mma_gemm<K, NTOT, RELU><<<grid, 256>>>(A, s_whi + woff, s_wlo + woff,
                                           bias, C, zout, eps, M);
}

extern "C" void kernel_launch(void* const* d_in, const int* in_sizes, int n_in,
                              void* d_out, int out_size) {
    const float* x       = (const float*)d_in[0];
    const void*  eidx    = d_in[1];
    const float* W_embed = (const float*)d_in[2];
    const float* eps1    = (const float*)d_in[3];
    const float* w1a     = (const float*)d_in[4];
    const float* b1a     = (const float*)d_in[5];
    const float* w1b     = (const float*)d_in[6];
    const float* b1b     = (const float*)d_in[7];
    const float* eps2    = (const float*)d_in[8];
    const float* w2a     = (const float*)d_in[9];
    const float* b2a     = (const float*)d_in[10];
    const float* w2b     = (const float*)d_in[11];
    const float* b2b     = (const float*)d_in[12];
    const float* eps3    = (const float*)d_in[13];
    const float* w3a     = (const float*)d_in[14];
    const float* b3a     = (const float*)d_in[15];
    const float* w3b     = (const float*)d_in[16];
    const float* b3b     = (const float*)d_in[17];

    const int M = in_sizes[0] / 64;          // 100000 nodes
    const int E = in_sizes[1] / 2;           // 1600000 edges

    float *ph, *pz, *pt;
    cudaGetSymbolAddress((void**)&ph, g_h);
    cudaGetSymbolAddress((void**)&pz, g_z);
    cudaGetSymbolAddress((void**)&pt, g_t);
    cudaGetSymbolAddress((void**)&s_whi, g_whi);
    cudaGetSymbolAddress((void**)&s_wlo, g_wlo);
    float* out = (float*)d_out;

    const int scatBlks = (E + 31) / 32;      // 4 edges/warp, 8 warps/block

    detect_kernel<<<1, 1>>>((const int*)eidx);

    // ---- prep all weights (hi/lo transposed bf16) ----
    // offsets: embed 0, w1a 8192, w1b 24576, w2a 40960, w2b 73728,
    //          w3a 106496, w3b 139264   (total 172032)
    WAll wa;
    wa.s[0] = {W_embed,  64, 128, 0};
    wa.s[1] = {w1a, 128, 128, 8192};
    wa.s[2] = {w1b, 128, 128, 24576};
    wa.s[3] = {w2a, 128, 256, 40960};
    wa.s[4] = {w2b, 256, 128, 73728};
    wa.s[5] = {w3a, 128, 256, 106496};
    wa.s[6] = {w3b, 256, 128, 139264};
    wprep_all<<<(WTOTAL + 255) / 256, 256>>>(wa, s_whi, s_wlo);

    // ---- embed: h = x @ W_embed ; z1 = (1+eps1)*h ----
    run_gemm<64, 128, false>(x, 0, nullptr, ph, pz, eps1, M);

    // ---- conv1 ----
    scatter_kernel<<<scatBlks, 256>>>(eidx, ph, pz, E);
    run_gemm<128, 128, true >(pz, 8192,  b1a, pt, nullptr, nullptr, M);
    run_gemm<128, 128, false>(pt, 24576, b1b, ph, pz, eps2, M);

    // ---- conv2 ----
    scatter_kernel<<<scatBlks, 256>>>(eidx, ph, pz, E);
    run_gemm<128, 256, true>(pz, 40960, b2a, pt, nullptr, nullptr, M);
    run_gemm<256, 128, true>(pt, 73728, b2b, ph, pz, eps3, M);

    // ---- conv3 ----
    scatter_kernel<<<scatBlks, 256>>>(eidx, ph, pz, E);
    run_gemm<128, 256, true>(pz, 106496, b3a, pt, nullptr, nullptr, M);
    run_gemm<256, 128, true>(pt, 139264, b3b, out, nullptr, nullptr, M);
}